// round 11
// baseline (speedup 1.0000x reference)
#include <cuda_runtime.h>
#include <math.h>

#define BLOCK_THREADS 128
#define DIRS_PER_THREAD 2
#define DIRS_PER_BLOCK (BLOCK_THREADS * DIRS_PER_THREAD)
#define MAX_COMP 64

__device__ __forceinline__ float ex2a(float x) {
    float r; asm("ex2.approx.ftz.f32 %0, %1;" : "=f"(r) : "f"(x)); return r;
}

__global__ void __launch_bounds__(BLOCK_THREADS, 12)
vmf_mixture_kernel(const float* __restrict__ lambdas,
                   const float* __restrict__ kappas,
                   const float* __restrict__ thetas,
                   const float* __restrict__ phis,
                   const float* __restrict__ wi,
                   float* __restrict__ out,
                   int S, int N)
{
    // per component: {ax, ay, az, b} with a = kappa*log2e folded into mu,
    // b = log2(lambda*norm) - a  (weight folded into the exponent)
    __shared__ float4 sC[MAX_COMP];

    int t = threadIdx.x;
    if (t < N) {
        float kappa = kappas[t];
        float lam   = lambdas[t];
        float th    = thetas[t];
        float ph    = phis[t];

        float st = sinf(th), ct = cosf(th);
        float sp = sinf(ph), cp = cosf(ph);

        float k = fmaxf(kappa, 1e-8f);
        float norm = (kappa < 1e-5f)
                   ? 0.07957747154594767f                       // 1/(4pi)
                   : k * 0.15915494309189535f / (1.0f - expf(-2.0f * k));
        float c = lam * norm;                                   // > 0 always

        const float LOG2E = 1.4426950408889634f;
        float a = kappa * LOG2E;
        float b = log2f(c) - a;
        sC[t] = make_float4(a * (st * cp), a * (st * sp), a * ct, b);
    }
    __syncthreads();

    int base = blockIdx.x * DIRS_PER_BLOCK + t;

    int i0 = base;
    int i1 = base + BLOCK_THREADS;
    int o0 = (i0 < S) ? 3 * i0 : 0;
    int o1 = (i1 < S) ? 3 * i1 : 0;
    float x0 = wi[o0 + 0], y0 = wi[o0 + 1], z0 = wi[o0 + 2];
    float x1 = wi[o1 + 0], y1 = wi[o1 + 1], z1 = wi[o1 + 2];

    // 4 accumulators: 2 per direction, alternating by comp parity,
    // so MUFU-result -> FADD chains are twice as slack.
    float acc0a = 0.0f, acc0b = 0.0f, acc1a = 0.0f, acc1b = 0.0f;

    #pragma unroll 16
    for (int n = 0; n < N; n += 2) {
        float4 ca = sC[n];
        float4 cb = sC[n + 1];

        float a0 = fmaf(ca.x, x0, fmaf(ca.y, y0, fmaf(ca.z, z0, ca.w)));
        float a1 = fmaf(ca.x, x1, fmaf(ca.y, y1, fmaf(ca.z, z1, ca.w)));
        float b0 = fmaf(cb.x, x0, fmaf(cb.y, y0, fmaf(cb.z, z0, cb.w)));
        float b1 = fmaf(cb.x, x1, fmaf(cb.y, y1, fmaf(cb.z, z1, cb.w)));

        acc0a += ex2a(a0);
        acc1a += ex2a(a1);
        acc0b += ex2a(b0);
        acc1b += ex2a(b1);
    }

    // odd-N tail (not hit for N=64)
    if (N & 1) {
        float4 ca = sC[N - 1];
        float a0 = fmaf(ca.x, x0, fmaf(ca.y, y0, fmaf(ca.z, z0, ca.w)));
        float a1 = fmaf(ca.x, x1, fmaf(ca.y, y1, fmaf(ca.z, z1, ca.w)));
        acc0a += ex2a(a0);
        acc1a += ex2a(a1);
    }

    if (i0 < S) out[i0] = acc0a + acc0b;
    if (i1 < S) out[i1] = acc1a + acc1b;
}

extern "C" void kernel_launch(void* const* d_in, const int* in_sizes, int n_in,
                              void* d_out, int out_size)
{
    const float* lambdas = (const float*)d_in[0];
    const float* kappas  = (const float*)d_in[1];
    const float* thetas  = (const float*)d_in[2];
    const float* phis    = (const float*)d_in[3];
    const float* wi      = (const float*)d_in[4];
    float* out = (float*)d_out;

    int N = in_sizes[0];
    int S = in_sizes[4] / 3;

    int blocks = (S + DIRS_PER_BLOCK - 1) / DIRS_PER_BLOCK;
    vmf_mixture_kernel<<<blocks, BLOCK_THREADS>>>(lambdas, kappas, thetas, phis, wi,
                                                  out, S, N);
}

// round 12
// speedup vs baseline: 1.1216x; 1.1216x over previous
#include <cuda_runtime.h>
#include <math.h>

#define BLOCK_THREADS 128
#define DIRS_PER_THREAD 2
#define DIRS_PER_BLOCK (BLOCK_THREADS * DIRS_PER_THREAD)
#define MAX_COMP 64

__device__ __forceinline__ float ex2a(float x) {
    float r; asm("ex2.approx.ftz.f32 %0, %1;" : "=f"(r) : "f"(x)); return r;
}

// acc += e via FFMA with immediate 1.0 multiplier: imm-form FFMA runs at
// rt_SMSP=1 on sm_103a (vs FADD rt=2) — halves accumulate cost on the FMA pipe.
// Rounding identical to FADD (multiply by 1.0 is exact).
__device__ __forceinline__ void acc_imm(float& acc, float e) {
    asm("fma.rn.f32 %0, %1, 0f3F800000, %0;" : "+f"(acc) : "f"(e));
}

__global__ void __launch_bounds__(BLOCK_THREADS, 16)
vmf_mixture_kernel(const float* __restrict__ lambdas,
                   const float* __restrict__ kappas,
                   const float* __restrict__ thetas,
                   const float* __restrict__ phis,
                   const float* __restrict__ wi,
                   float* __restrict__ out,
                   int S, int N)
{
    // per component: {ax, ay, az, b} with a = kappa*log2e folded into mu,
    // b = log2(lambda*norm) - a  (weight folded into the exponent)
    __shared__ float4 sC[MAX_COMP];

    int t = threadIdx.x;
    if (t < N) {
        float kappa = kappas[t];
        float lam   = lambdas[t];
        float th    = thetas[t];
        float ph    = phis[t];

        float st = sinf(th), ct = cosf(th);
        float sp = sinf(ph), cp = cosf(ph);

        float k = fmaxf(kappa, 1e-8f);
        float norm = (kappa < 1e-5f)
                   ? 0.07957747154594767f                       // 1/(4pi)
                   : k * 0.15915494309189535f / (1.0f - expf(-2.0f * k));
        float c = lam * norm;                                   // > 0 always

        const float LOG2E = 1.4426950408889634f;
        float a = kappa * LOG2E;
        float b = log2f(c) - a;
        sC[t] = make_float4(a * (st * cp), a * (st * sp), a * ct, b);
    }
    __syncthreads();

    int base = blockIdx.x * DIRS_PER_BLOCK + t;

    int i0 = base;
    int i1 = base + BLOCK_THREADS;
    int o0 = (i0 < S) ? 3 * i0 : 0;
    int o1 = (i1 < S) ? 3 * i1 : 0;
    float x0 = wi[o0 + 0], y0 = wi[o0 + 1], z0 = wi[o0 + 2];
    float x1 = wi[o1 + 0], y1 = wi[o1 + 1], z1 = wi[o1 + 2];

    float acc0 = 0.0f, acc1 = 0.0f;

    #pragma unroll 4
    for (int n = 0; n < N; n++) {
        float4 c = sC[n];
        float a0 = fmaf(c.x, x0, fmaf(c.y, y0, fmaf(c.z, z0, c.w)));
        float a1 = fmaf(c.x, x1, fmaf(c.y, y1, fmaf(c.z, z1, c.w)));
        acc_imm(acc0, ex2a(a0));
        acc_imm(acc1, ex2a(a1));
    }

    if (i0 < S) out[i0] = acc0;
    if (i1 < S) out[i1] = acc1;
}

extern "C" void kernel_launch(void* const* d_in, const int* in_sizes, int n_in,
                              void* d_out, int out_size)
{
    const float* lambdas = (const float*)d_in[0];
    const float* kappas  = (const float*)d_in[1];
    const float* thetas  = (const float*)d_in[2];
    const float* phis    = (const float*)d_in[3];
    const float* wi      = (const float*)d_in[4];
    float* out = (float*)d_out;

    int N = in_sizes[0];
    int S = in_sizes[4] / 3;

    int blocks = (S + DIRS_PER_BLOCK - 1) / DIRS_PER_BLOCK;
    vmf_mixture_kernel<<<blocks, BLOCK_THREADS>>>(lambdas, kappas, thetas, phis, wi,
                                                  out, S, N);
}